// round 2
// baseline (speedup 1.0000x reference)
#include <cuda_runtime.h>

#define N_EDGES 50000
#define N_NODESC 100000

typedef unsigned long long ull;

// Scratch
__device__ float g_s;                        // inter_nw scalar
__device__ float4 g_e1[N_EDGES * 32];        // e1 [E,128]

// ---------------------------------------------------------------------------
// packed f32x2 helpers
// ---------------------------------------------------------------------------
__device__ __forceinline__ ull pk2(float lo, float hi) {
    ull r; asm("mov.b64 %0,{%1,%2};" : "=l"(r) : "f"(lo), "f"(hi)); return r;
}
__device__ __forceinline__ void upk2(ull v, float& lo, float& hi) {
    asm("mov.b64 {%0,%1},%2;" : "=f"(lo), "=f"(hi) : "l"(v));
}
__device__ __forceinline__ void fma2(ull& d, ull a, ull b) {
    asm("fma.rn.f32x2 %0,%1,%2,%0;" : "+l"(d) : "l"(a), "l"(b));
}

// ---------------------------------------------------------------------------
// inter_nw = mean_i cos(w3[i], w3[0])
// ---------------------------------------------------------------------------
__global__ void k_internw(const float* __restrict__ w3) {
    __shared__ float tv[128];
    __shared__ float red[128];
    __shared__ float ntv2;
    int i = threadIdx.x;
    tv[i] = w3[i];
    __syncthreads();
    float dot = 0.f, nrm = 0.f;
#pragma unroll 16
    for (int j = 0; j < 128; j++) {
        float wv = w3[i * 128 + j];
        dot += wv * tv[j];
        nrm += wv * wv;
    }
    if (i == 0) ntv2 = nrm;
    __syncthreads();
    float cosv = dot / (sqrtf(ntv2) * sqrtf(nrm));
    red[i] = cosv;
    __syncthreads();
    for (int s = 64; s > 0; s >>= 1) {
        if (i < s) red[i] += red[i + s];
        __syncthreads();
    }
    if (i == 0) g_s = red[0] * (1.0f / 128.0f);
}

// ---------------------------------------------------------------------------
// Fused: gather(x,seq) -> relu(s * A@W1) -> @W2 -> e1
// 64 rows/block, 256 threads. A lives transposed in smem the whole time.
//   AsT: [128 k][66 pad] fp32  (33792 B)
//   WsD: [32 k][128 c]  ull dup pairs (32768 B)
// ---------------------------------------------------------------------------
#define ROWPAD 66
#define SMEM_A (128 * ROWPAD)            // floats
#define SMEM_BYTES (SMEM_A * 4 + 32 * 128 * 8)

__global__ void __launch_bounds__(256)
k_fused(const float4* __restrict__ x, const int* __restrict__ seq,
        const float* __restrict__ w1, const float* __restrict__ w2,
        float* __restrict__ e1, int M) {
    extern __shared__ __align__(16) char smem[];
    float* AsT = (float*)smem;                       // [k][row]
    ull*   WsD = (ull*)(smem + SMEM_A * 4);          // [k][c] dup

    int t = threadIdx.x;
    int lane = t & 31;
    int wid = t >> 5;
    int row0 = blockIdx.x * 64;

    // ---- Phase 1: gather 64 rows of edge_pre, store transposed ----
    for (int rr = wid; rr < 64; rr += 8) {
        int row = row0 + rr;
        int idx = 0;
        if (row < M) idx = seq[row * 32 + lane];
        unsigned on = __ballot_sync(0xffffffffu, idx > 0);
        int cnt = __popc(on);
        float wn = cnt ? (1.0f / (float)cnt) : 0.0f;
        float zfill = cnt ? 0.0f : (1.0f / 32.0f);

        float4 acc = make_float4(0.f, 0.f, 0.f, 0.f);
#pragma unroll
        for (int a = 0; a < 32; a++) {
            int ia = __shfl_sync(0xffffffffu, idx, a);
            float wa = ((on >> a) & 1u) ? wn : zfill;
            float4 v = x[ia * 32 + lane];
            acc.x += wa * v.x; acc.y += wa * v.y;
            acc.z += wa * v.z; acc.w += wa * v.w;
        }
        int kb = lane * 4;
        AsT[(kb + 0) * ROWPAD + rr] = acc.x;
        AsT[(kb + 1) * ROWPAD + rr] = acc.y;
        AsT[(kb + 2) * ROWPAD + rr] = acc.z;
        AsT[(kb + 3) * ROWPAD + rr] = acc.w;
    }
    __syncthreads();

    int tx = t & 31;       // col group: cols tx*4..tx*4+3
    int ty = t >> 5;       // row group: rows ty*8..ty*8+7 (pairs 2p,2p+1)

    // ================= GEMM 1: AsT @ W1, relu(scale) ==================
    ull acc2[4][4];
#pragma unroll
    for (int p = 0; p < 4; p++)
#pragma unroll
        for (int c = 0; c < 4; c++) acc2[p][c] = 0ull;

    for (int kc = 0; kc < 128; kc += 32) {
        // load W1 chunk, duplicated
        for (int i = t; i < 1024; i += 256) {
            int k = i >> 5, c4 = i & 31;
            float4 wv = *(const float4*)&w1[(kc + k) * 128 + c4 * 4];
            ull* dst = &WsD[k * 128 + c4 * 4];
            dst[0] = pk2(wv.x, wv.x); dst[1] = pk2(wv.y, wv.y);
            dst[2] = pk2(wv.z, wv.z); dst[3] = pk2(wv.w, wv.w);
        }
        __syncthreads();
#pragma unroll 2
        for (int k = 0; k < 32; k++) {
            const float* arow = &AsT[(kc + k) * ROWPAD + ty * 8];
            ull a0 = *(const ull*)&arow[0];
            ull a1 = *(const ull*)&arow[2];
            ull a2 = *(const ull*)&arow[4];
            ull a3 = *(const ull*)&arow[6];
            ulonglong2 wA = *(const ulonglong2*)&WsD[k * 128 + tx * 4];
            ulonglong2 wB = *(const ulonglong2*)&WsD[k * 128 + tx * 4 + 2];
            fma2(acc2[0][0], a0, wA.x); fma2(acc2[0][1], a0, wA.y);
            fma2(acc2[0][2], a0, wB.x); fma2(acc2[0][3], a0, wB.y);
            fma2(acc2[1][0], a1, wA.x); fma2(acc2[1][1], a1, wA.y);
            fma2(acc2[1][2], a1, wB.x); fma2(acc2[1][3], a1, wB.y);
            fma2(acc2[2][0], a2, wA.x); fma2(acc2[2][1], a2, wA.y);
            fma2(acc2[2][2], a2, wB.x); fma2(acc2[2][3], a2, wB.y);
            fma2(acc2[3][0], a3, wA.x); fma2(acc2[3][1], a3, wA.y);
            fma2(acc2[3][2], a3, wB.x); fma2(acc2[3][3], a3, wB.y);
        }
        __syncthreads();
    }

    // relu(s * acc) -> AsT transposed (new k-dim = old col-dim)
    float s = g_s;
#pragma unroll
    for (int p = 0; p < 4; p++)
#pragma unroll
        for (int c = 0; c < 4; c++) {
            float lo, hi;
            upk2(acc2[p][c], lo, hi);
            lo = fmaxf(lo * s, 0.f);
            hi = fmaxf(hi * s, 0.f);
            *(ull*)&AsT[(tx * 4 + c) * ROWPAD + ty * 8 + 2 * p] = pk2(lo, hi);
            acc2[p][c] = 0ull;
        }
    __syncthreads();

    // ================= GEMM 2: AsT @ W2 -> e1 (global) ================
    for (int kc = 0; kc < 128; kc += 32) {
        for (int i = t; i < 1024; i += 256) {
            int k = i >> 5, c4 = i & 31;
            float4 wv = *(const float4*)&w2[(kc + k) * 128 + c4 * 4];
            ull* dst = &WsD[k * 128 + c4 * 4];
            dst[0] = pk2(wv.x, wv.x); dst[1] = pk2(wv.y, wv.y);
            dst[2] = pk2(wv.z, wv.z); dst[3] = pk2(wv.w, wv.w);
        }
        __syncthreads();
#pragma unroll 2
        for (int k = 0; k < 32; k++) {
            const float* arow = &AsT[(kc + k) * ROWPAD + ty * 8];
            ull a0 = *(const ull*)&arow[0];
            ull a1 = *(const ull*)&arow[2];
            ull a2 = *(const ull*)&arow[4];
            ull a3 = *(const ull*)&arow[6];
            ulonglong2 wA = *(const ulonglong2*)&WsD[k * 128 + tx * 4];
            ulonglong2 wB = *(const ulonglong2*)&WsD[k * 128 + tx * 4 + 2];
            fma2(acc2[0][0], a0, wA.x); fma2(acc2[0][1], a0, wA.y);
            fma2(acc2[0][2], a0, wB.x); fma2(acc2[0][3], a0, wB.y);
            fma2(acc2[1][0], a1, wA.x); fma2(acc2[1][1], a1, wA.y);
            fma2(acc2[1][2], a1, wB.x); fma2(acc2[1][3], a1, wB.y);
            fma2(acc2[2][0], a2, wA.x); fma2(acc2[2][1], a2, wA.y);
            fma2(acc2[2][2], a2, wB.x); fma2(acc2[2][3], a2, wB.y);
            fma2(acc2[3][0], a3, wA.x); fma2(acc2[3][1], a3, wA.y);
            fma2(acc2[3][2], a3, wB.x); fma2(acc2[3][3], a3, wB.y);
        }
        __syncthreads();
    }

    // write e1: rows ty*8+r, cols tx*4..+3
#pragma unroll
    for (int r = 0; r < 8; r++) {
        int gr = row0 + ty * 8 + r;
        if (gr < M) {
            int p = r >> 1, h = r & 1;
            float4 o;
            float lo, hi;
            upk2(acc2[p][0], lo, hi); o.x = h ? hi : lo;
            upk2(acc2[p][1], lo, hi); o.y = h ? hi : lo;
            upk2(acc2[p][2], lo, hi); o.z = h ? hi : lo;
            upk2(acc2[p][3], lo, hi); o.w = h ? hi : lo;
            *(float4*)&e1[gr * 128 + tx * 4] = o;
        }
    }
}

// ---------------------------------------------------------------------------
// Final masked-mean gather: out[n] = sum_k w_k * e1[useq[n,k]]
// ---------------------------------------------------------------------------
__global__ void k_gather16(const float4* __restrict__ src,
                           const int* __restrict__ idxmat,
                           float4* __restrict__ dst, int rows) {
    int w = (blockIdx.x * blockDim.x + threadIdx.x) >> 5;
    int lane = threadIdx.x & 31;
    if (w >= rows) return;

    int idx = 0;
    if (lane < 16) idx = idxmat[w * 16 + lane];
    unsigned on = __ballot_sync(0xffffffffu, (lane < 16) && (idx > 0));
    int cnt = __popc(on);
    float wn = cnt ? (1.0f / (float)cnt) : 0.0f;
    float zfill = cnt ? 0.0f : (1.0f / 16.0f);

    float4 acc = make_float4(0.f, 0.f, 0.f, 0.f);
#pragma unroll
    for (int a = 0; a < 16; a++) {
        int ia = __shfl_sync(0xffffffffu, idx, a);
        float wa = ((on >> a) & 1u) ? wn : zfill;
        float4 v = src[ia * 32 + lane];
        acc.x += wa * v.x; acc.y += wa * v.y;
        acc.z += wa * v.z; acc.w += wa * v.w;
    }
    dst[w * 32 + lane] = acc;
}

// ---------------------------------------------------------------------------
extern "C" void kernel_launch(void* const* d_in, const int* in_sizes, int n_in,
                              void* d_out, int out_size) {
    const float* x    = (const float*)d_in[0];   // [100000,128]
    const int*   seq  = (const int*)d_in[1];     // [50000,32]
    const int*   useq = (const int*)d_in[2];     // [100000,16]
    const float* w1   = (const float*)d_in[4];   // [128,128]
    const float* w2   = (const float*)d_in[5];   // [128,128]
    const float* w3   = (const float*)d_in[6];   // [128,128]
    float* out = (float*)d_out;

    void* p_e1;
    cudaGetSymbolAddress(&p_e1, g_e1);

    cudaFuncSetAttribute(k_fused, cudaFuncAttributeMaxDynamicSharedMemorySize,
                         SMEM_BYTES);

    k_internw<<<1, 128>>>(w3);

    k_fused<<<(N_EDGES + 63) / 64, 256, SMEM_BYTES>>>(
        (const float4*)x, seq, w1, w2, (float*)p_e1, N_EDGES);

    k_gather16<<<(N_NODESC + 7) / 8, 256>>>((const float4*)p_e1, useq,
                                            (float4*)out, N_NODESC);
}

// round 4
// speedup vs baseline: 1.8072x; 1.8072x over previous
#include <cuda_runtime.h>
#include <cstdint>

#define N_EDGES   50000
#define N_NODESC  100000
#define TILES     ((N_EDGES + 127) / 128)     // 391
#define ROWS_PAD  (TILES * 128)               // 50048

// ---------------- device scratch (allocation-free) ----------------
__device__ float  g_s;
__device__ float4 g_edge_pre[ROWS_PAD * 32];  // [50048,128] gathered means
__device__ float4 g_e1[N_EDGES * 32];         // [50000,128]

// ---------------- helpers ----------------
__device__ __forceinline__ uint32_t to_tf32(float f) {
    uint32_t r;
    asm("cvt.rna.tf32.f32 %0, %1;" : "=r"(r) : "f"(f));
    return r;
}

// m16n8k8 tf32 mma, fp32 accumulate (sm_80+ baseline feature)
__device__ __forceinline__ void mma8(float* c, const uint32_t* a,
                                     uint32_t b0, uint32_t b1) {
    asm volatile(
        "mma.sync.aligned.m16n8k8.row.col.f32.tf32.tf32.f32 "
        "{%0,%1,%2,%3},{%4,%5,%6,%7},{%8,%9},{%0,%1,%2,%3};"
        : "+f"(c[0]), "+f"(c[1]), "+f"(c[2]), "+f"(c[3])
        : "r"(a[0]), "r"(a[1]), "r"(a[2]), "r"(a[3]), "r"(b0), "r"(b1));
}

// ---------------------------------------------------------------------------
// inter_nw = mean_i cos(w3[i], w3[0])   (coalesced, warp-reduced)
// ---------------------------------------------------------------------------
__global__ void k_internw(const float* __restrict__ w3) {
    __shared__ float sdot[128], snrm[128], red[4];
    int t = threadIdx.x, w = t >> 5, lane = t & 31;   // 512 threads
    for (int row = w; row < 128; row += 16) {
        float d = 0.f, n = 0.f;
#pragma unroll
        for (int jj = 0; jj < 4; jj++) {
            int j = jj * 32 + lane;
            float v = w3[row * 128 + j];
            d += v * w3[j];
            n += v * v;
        }
#pragma unroll
        for (int o = 16; o; o >>= 1) {
            d += __shfl_xor_sync(0xffffffffu, d, o);
            n += __shfl_xor_sync(0xffffffffu, n, o);
        }
        if (lane == 0) { sdot[row] = d; snrm[row] = n; }
    }
    __syncthreads();
    if (t < 128) {
        float c = sdot[t] / (sqrtf(snrm[0]) * sqrtf(snrm[t]));
#pragma unroll
        for (int o = 16; o; o >>= 1) c += __shfl_xor_sync(0xffffffffu, c, o);
        if (lane == 0) red[t >> 5] = c;
    }
    __syncthreads();
    if (t == 0) g_s = (red[0] + red[1] + red[2] + red[3]) * (1.0f / 128.0f);
}

// ---------------------------------------------------------------------------
// Masked-mean gathers (proven R1 kernels)
// ---------------------------------------------------------------------------
template <int ARITY>
__global__ void k_gather(const float4* __restrict__ src,
                         const int* __restrict__ idxmat,
                         float4* __restrict__ dst, int rows) {
    int w = (blockIdx.x * blockDim.x + threadIdx.x) >> 5;
    int lane = threadIdx.x & 31;
    if (w >= rows) return;

    int idx = 0;
    if (lane < ARITY) idx = idxmat[w * ARITY + lane];
    unsigned on = __ballot_sync(0xffffffffu, (lane < ARITY) && (idx > 0));
    int cnt = __popc(on);
    float wn = cnt ? (1.0f / (float)cnt) : (1.0f / (float)ARITY);

    float4 acc = make_float4(0.f, 0.f, 0.f, 0.f);
#pragma unroll
    for (int a = 0; a < ARITY; a++) {
        int ia = __shfl_sync(0xffffffffu, idx, a);
        float wa = cnt ? (((on >> a) & 1u) ? wn : 0.0f) : wn;
        float4 v = src[ia * 32 + lane];
        acc.x += wa * v.x; acc.y += wa * v.y;
        acc.z += wa * v.z; acc.w += wa * v.w;
    }
    dst[w * 32 + lane] = acc;
}

// ---------------------------------------------------------------------------
// Fused dual GEMM (tf32 mma.sync): e1 = relu(s * A@W1) @ W2
// 128 rows/CTA, 256 threads (8 warps), warp tile 32x64.
//   sA  [128][132] fp32-as-tf32 (A, later T1)
//   sW1 [128][136], sW2 [128][136]
// ---------------------------------------------------------------------------
#define PA 132
#define PW 136
#define SA_FLOATS  (128 * PA)
#define SW_FLOATS  (128 * PW)
#define SMEM_TOTAL ((SA_FLOATS + 2 * SW_FLOATS) * 4)

__device__ __forceinline__ void do_gemm(const float* sSrc, const float* sW,
                                        float acc[2][8][4],
                                        int mrow0, int ncol0,
                                        int gid, int tig) {
    const float* pa = sSrc + (mrow0 + gid) * PA + tig;
    const float* pb = sW + tig * PW + ncol0 + gid;
#pragma unroll
    for (int k0 = 0; k0 < 128; k0 += 8) {
        uint32_t a[2][4];
#pragma unroll
        for (int s = 0; s < 2; s++) {
            const float* p = pa + s * 16 * PA + k0;
            a[s][0] = __float_as_uint(p[0]);
            a[s][1] = __float_as_uint(p[8 * PA]);
            a[s][2] = __float_as_uint(p[4]);
            a[s][3] = __float_as_uint(p[8 * PA + 4]);
        }
        const float* q = pb + k0 * PW;
#pragma unroll
        for (int n = 0; n < 8; n++) {
            uint32_t b0 = __float_as_uint(q[n * 8]);
            uint32_t b1 = __float_as_uint(q[4 * PW + n * 8]);
            mma8(acc[0][n], a[0], b0, b1);
            mma8(acc[1][n], a[1], b0, b1);
        }
    }
}

__global__ void __launch_bounds__(256)
k_dualgemm(const float* __restrict__ Ain, const float* __restrict__ w1,
           const float* __restrict__ w2, float* __restrict__ e1, int M) {
    extern __shared__ __align__(16) float smem[];
    float* sA  = smem;
    float* sW1 = smem + SA_FLOATS;
    float* sW2 = sW1 + SW_FLOATS;

    int t = threadIdx.x;
    int w = t >> 5, lane = t & 31;
    int gid = lane >> 2, tig = lane & 3;
    int row0 = blockIdx.x * 128;

    // ---- load A tile + both weights (tf32-converted) ----
    for (int i = t; i < 4096; i += 256) {
        int k = i >> 5, q = (i & 31) * 4;
        float4 v1 = *(const float4*)&w1[k * 128 + q];
        float4 v2 = *(const float4*)&w2[k * 128 + q];
        float4 va = *(const float4*)&Ain[(size_t)(row0 + k) * 128 + q];
        uint4 u1 = make_uint4(to_tf32(v1.x), to_tf32(v1.y), to_tf32(v1.z), to_tf32(v1.w));
        uint4 u2 = make_uint4(to_tf32(v2.x), to_tf32(v2.y), to_tf32(v2.z), to_tf32(v2.w));
        uint4 ua = make_uint4(to_tf32(va.x), to_tf32(va.y), to_tf32(va.z), to_tf32(va.w));
        *(uint4*)&sW1[k * PW + q] = u1;
        *(uint4*)&sW2[k * PW + q] = u2;
        *(uint4*)&sA[k * PA + q]  = ua;
    }
    __syncthreads();

    int mrow0 = (w & 3) * 32;       // warp row strip
    int ncol0 = (w >> 2) * 64;      // warp col half

    float acc[2][8][4];
#pragma unroll
    for (int s = 0; s < 2; s++)
#pragma unroll
        for (int n = 0; n < 8; n++)
#pragma unroll
            for (int j = 0; j < 4; j++) acc[s][n][j] = 0.f;

    // ================= GEMM 1 =================
    do_gemm(sA, sW1, acc, mrow0, ncol0, gid, tig);

    float s_nw = g_s;
    __syncthreads();    // everyone done reading A before overwrite

    // relu(s * acc) -> sA (tf32), then clear accs
#pragma unroll
    for (int s = 0; s < 2; s++) {
#pragma unroll
        for (int n = 0; n < 8; n++) {
            int r0 = mrow0 + s * 16 + gid;
            int c0 = ncol0 + n * 8 + 2 * tig;
            uint2 lo = make_uint2(
                to_tf32(fmaxf(acc[s][n][0] * s_nw, 0.f)),
                to_tf32(fmaxf(acc[s][n][1] * s_nw, 0.f)));
            uint2 hi = make_uint2(
                to_tf32(fmaxf(acc[s][n][2] * s_nw, 0.f)),
                to_tf32(fmaxf(acc[s][n][3] * s_nw, 0.f)));
            *(uint2*)&sA[r0 * PA + c0] = lo;
            *(uint2*)&sA[(r0 + 8) * PA + c0] = hi;
#pragma unroll
            for (int j = 0; j < 4; j++) acc[s][n][j] = 0.f;
        }
    }
    __syncthreads();

    // ================= GEMM 2 =================
    do_gemm(sA, sW2, acc, mrow0, ncol0, gid, tig);

    // write e1
#pragma unroll
    for (int s = 0; s < 2; s++) {
#pragma unroll
        for (int n = 0; n < 8; n++) {
            int r = row0 + mrow0 + s * 16 + gid;
            int c = ncol0 + n * 8 + 2 * tig;
            if (r < M)
                *(float2*)&e1[(size_t)r * 128 + c] =
                    make_float2(acc[s][n][0], acc[s][n][1]);
            if (r + 8 < M)
                *(float2*)&e1[(size_t)(r + 8) * 128 + c] =
                    make_float2(acc[s][n][2], acc[s][n][3]);
        }
    }
}

// ---------------------------------------------------------------------------
extern "C" void kernel_launch(void* const* d_in, const int* in_sizes, int n_in,
                              void* d_out, int out_size) {
    const float* x    = (const float*)d_in[0];   // [100000,128]
    const int*   seq  = (const int*)d_in[1];     // [50000,32]
    const int*   useq = (const int*)d_in[2];     // [100000,16]
    const float* w1   = (const float*)d_in[4];   // [128,128]
    const float* w2   = (const float*)d_in[5];   // [128,128]
    const float* w3   = (const float*)d_in[6];   // [128,128]
    float* out = (float*)d_out;

    void *p_edge_pre, *p_e1;
    cudaGetSymbolAddress(&p_edge_pre, g_edge_pre);
    cudaGetSymbolAddress(&p_e1, g_e1);

    cudaFuncSetAttribute(k_dualgemm,
                         cudaFuncAttributeMaxDynamicSharedMemorySize,
                         SMEM_TOTAL);

    k_internw<<<1, 512>>>(w3);

    // edge_pre[e] = masked-mean_a x[seq[e,a]]
    k_gather<32><<<(N_EDGES + 7) / 8, 256>>>((const float4*)x, seq,
                                             (float4*)p_edge_pre, N_EDGES);

    // e1 = relu(s * edge_pre @ W1) @ W2   (tf32 mma.sync)
    k_dualgemm<<<TILES, 256, SMEM_TOTAL>>>((const float*)p_edge_pre, w1, w2,
                                           (float*)p_e1, N_EDGES);

    // out[n] = masked-mean_k e1[useq[n,k]]
    k_gather<16><<<(N_NODESC + 7) / 8, 256>>>((const float4*)p_e1, useq,
                                              (float4*)out, N_NODESC);
}

// round 8
// speedup vs baseline: 2.1524x; 1.1910x over previous
#include <cuda_runtime.h>
#include <cuda_fp16.h>
#include <cstdint>

#define N_EDGES   50000
#define N_NODESC  100000
#define TILES     ((N_EDGES + 127) / 128)     // 391
#define ROWS_PAD  (TILES * 128)               // 50048

// ---------------- device scratch (allocation-free) ----------------
__device__ float  g_s;
__device__ uint2  g_xh[N_NODESC * 32];        // x as fp16 [100000,128]
__device__ float4 g_edge_pre[ROWS_PAD * 32];  // [50048,128] gathered means
__device__ uint2  g_e1h[N_EDGES * 32];        // e1 as fp16 [50000,128]

// ---------------- helpers ----------------
__device__ __forceinline__ uint32_t to_tf32(float f) {
    uint32_t r;
    asm("cvt.rna.tf32.f32 %0, %1;" : "=r"(r) : "f"(f));
    return r;
}
__device__ __forceinline__ void mma8(float* c, const uint32_t* a,
                                     uint32_t b0, uint32_t b1) {
    asm volatile(
        "mma.sync.aligned.m16n8k8.row.col.f32.tf32.tf32.f32 "
        "{%0,%1,%2,%3},{%4,%5,%6,%7},{%8,%9},{%0,%1,%2,%3};"
        : "+f"(c[0]), "+f"(c[1]), "+f"(c[2]), "+f"(c[3])
        : "r"(a[0]), "r"(a[1]), "r"(a[2]), "r"(a[3]), "r"(b0), "r"(b1));
}

// ---------------------------------------------------------------------------
// inter_nw = mean_i cos(w3[i], w3[0])
// ---------------------------------------------------------------------------
__global__ void k_internw(const float* __restrict__ w3) {
    __shared__ float sdot[128], snrm[128], red[4];
    int t = threadIdx.x, w = t >> 5, lane = t & 31;   // 512 threads
    for (int row = w; row < 128; row += 16) {
        float d = 0.f, n = 0.f;
#pragma unroll
        for (int jj = 0; jj < 4; jj++) {
            int j = jj * 32 + lane;
            float v = w3[row * 128 + j];
            d += v * w3[j];
            n += v * v;
        }
#pragma unroll
        for (int o = 16; o; o >>= 1) {
            d += __shfl_xor_sync(0xffffffffu, d, o);
            n += __shfl_xor_sync(0xffffffffu, n, o);
        }
        if (lane == 0) { sdot[row] = d; snrm[row] = n; }
    }
    __syncthreads();
    if (t < 128) {
        float c = sdot[t] / (sqrtf(snrm[0]) * sqrtf(snrm[t]));
#pragma unroll
        for (int o = 16; o; o >>= 1) c += __shfl_xor_sync(0xffffffffu, c, o);
        if (lane == 0) red[t >> 5] = c;
    }
    __syncthreads();
    if (t == 0) g_s = (red[0] + red[1] + red[2] + red[3]) * (1.0f / 128.0f);
}

// ---------------------------------------------------------------------------
// fp32 -> fp16 table convert (x)
// ---------------------------------------------------------------------------
__global__ void k_tohalf(const float4* __restrict__ src,
                         uint2* __restrict__ dst, int n4) {
    int i = blockIdx.x * blockDim.x + threadIdx.x;
    if (i >= n4) return;
    float4 v = src[i];
    __half2 a = __floats2half2_rn(v.x, v.y);
    __half2 b = __floats2half2_rn(v.z, v.w);
    dst[i] = make_uint2(*(uint32_t*)&a, *(uint32_t*)&b);
}

// ---------------------------------------------------------------------------
// Masked-mean gather over fp16 rows (128 halfs = 32 uint2 per row).
// One warp per output row; lane owns cols 4*lane..4*lane+3. fp32 accumulate.
// ---------------------------------------------------------------------------
template <int ARITY>
__global__ void k_gather_h(const uint2* __restrict__ src,
                           const int* __restrict__ idxmat,
                           float4* __restrict__ dst, int rows) {
    int w = (blockIdx.x * blockDim.x + threadIdx.x) >> 5;
    int lane = threadIdx.x & 31;
    if (w >= rows) return;

    int idx = 0;
    if (lane < ARITY) idx = idxmat[w * ARITY + lane];
    unsigned on = __ballot_sync(0xffffffffu, (lane < ARITY) && (idx > 0));
    int cnt = __popc(on);
    float wn = cnt ? (1.0f / (float)cnt) : (1.0f / (float)ARITY);

    float4 acc = make_float4(0.f, 0.f, 0.f, 0.f);
#pragma unroll
    for (int a = 0; a < ARITY; a++) {
        int ia = __shfl_sync(0xffffffffu, idx, a);
        float wa = cnt ? (((on >> a) & 1u) ? wn : 0.0f) : wn;
        uint2 u = src[ia * 32 + lane];
        float2 f0 = __half22float2(*(__half2*)&u.x);
        float2 f1 = __half22float2(*(__half2*)&u.y);
        acc.x += wa * f0.x; acc.y += wa * f0.y;
        acc.z += wa * f1.x; acc.w += wa * f1.y;
    }
    dst[w * 32 + lane] = acc;
}

// ---------------------------------------------------------------------------
// Fused dual GEMM (tf32 mma.sync): e1 = relu(s * A@W1) @ W2  -> fp16
// 128 rows/CTA, 512 threads (16 warps), warp tile 32x32.
// ---------------------------------------------------------------------------
#define PA 132
#define PW 136
#define SA_FLOATS  (128 * PA)
#define SW_FLOATS  (128 * PW)
#define SMEM_TOTAL ((SA_FLOATS + 2 * SW_FLOATS) * 4)

__device__ __forceinline__ void do_gemm(const float* sSrc, const float* sW,
                                        float acc[2][4][4],
                                        int mrow0, int ncol0,
                                        int gid, int tig) {
    const float* pa = sSrc + (mrow0 + gid) * PA + tig;
    const float* pb = sW + tig * PW + ncol0 + gid;
#pragma unroll
    for (int k0 = 0; k0 < 128; k0 += 8) {
        uint32_t a[2][4];
#pragma unroll
        for (int s = 0; s < 2; s++) {
            const float* p = pa + s * 16 * PA + k0;
            a[s][0] = __float_as_uint(p[0]);
            a[s][1] = __float_as_uint(p[8 * PA]);
            a[s][2] = __float_as_uint(p[4]);
            a[s][3] = __float_as_uint(p[8 * PA + 4]);
        }
        const float* q = pb + k0 * PW;
#pragma unroll
        for (int n = 0; n < 4; n++) {
            uint32_t b0 = __float_as_uint(q[n * 8]);
            uint32_t b1 = __float_as_uint(q[4 * PW + n * 8]);
            mma8(acc[0][n], a[0], b0, b1);
            mma8(acc[1][n], a[1], b0, b1);
        }
    }
}

__global__ void __launch_bounds__(512)
k_dualgemm(const float* __restrict__ Ain, const float* __restrict__ w1,
           const float* __restrict__ w2, __half2* __restrict__ e1h, int M) {
    extern __shared__ __align__(16) float smem[];
    float* sA  = smem;
    float* sW1 = smem + SA_FLOATS;
    float* sW2 = sW1 + SW_FLOATS;

    int t = threadIdx.x;
    int w = t >> 5, lane = t & 31;
    int gid = lane >> 2, tig = lane & 3;
    int row0 = blockIdx.x * 128;

    for (int i = t; i < 4096; i += 512) {
        int k = i >> 5, q = (i & 31) * 4;
        float4 v1 = *(const float4*)&w1[k * 128 + q];
        float4 v2 = *(const float4*)&w2[k * 128 + q];
        float4 va = *(const float4*)&Ain[(size_t)(row0 + k) * 128 + q];
        uint4 u1 = make_uint4(to_tf32(v1.x), to_tf32(v1.y), to_tf32(v1.z), to_tf32(v1.w));
        uint4 u2 = make_uint4(to_tf32(v2.x), to_tf32(v2.y), to_tf32(v2.z), to_tf32(v2.w));
        uint4 ua = make_uint4(to_tf32(va.x), to_tf32(va.y), to_tf32(va.z), to_tf32(va.w));
        *(uint4*)&sW1[k * PW + q] = u1;
        *(uint4*)&sW2[k * PW + q] = u2;
        *(uint4*)&sA[k * PA + q]  = ua;
    }
    __syncthreads();

    int mrow0 = (w & 3) * 32;       // warp row strip
    int ncol0 = (w >> 2) * 32;      // warp col quarter

    float acc[2][4][4];
#pragma unroll
    for (int s = 0; s < 2; s++)
#pragma unroll
        for (int n = 0; n < 4; n++)
#pragma unroll
            for (int j = 0; j < 4; j++) acc[s][n][j] = 0.f;

    // ================= GEMM 1 =================
    do_gemm(sA, sW1, acc, mrow0, ncol0, gid, tig);

    float s_nw = g_s;
    __syncthreads();    // all reads of A done before overwrite

    // relu(s * acc) -> sA (tf32)
#pragma unroll
    for (int s = 0; s < 2; s++) {
#pragma unroll
        for (int n = 0; n < 4; n++) {
            int r0 = mrow0 + s * 16 + gid;
            int c0 = ncol0 + n * 8 + 2 * tig;
            uint2 lo = make_uint2(
                to_tf32(fmaxf(acc[s][n][0] * s_nw, 0.f)),
                to_tf32(fmaxf(acc[s][n][1] * s_nw, 0.f)));
            uint2 hi = make_uint2(
                to_tf32(fmaxf(acc[s][n][2] * s_nw, 0.f)),
                to_tf32(fmaxf(acc[s][n][3] * s_nw, 0.f)));
            *(uint2*)&sA[r0 * PA + c0] = lo;
            *(uint2*)&sA[(r0 + 8) * PA + c0] = hi;
#pragma unroll
            for (int j = 0; j < 4; j++) acc[s][n][j] = 0.f;
        }
    }
    __syncthreads();

    // ================= GEMM 2 =================
    do_gemm(sA, sW2, acc, mrow0, ncol0, gid, tig);

    // write e1 (fp16)
#pragma unroll
    for (int s = 0; s < 2; s++) {
#pragma unroll
        for (int n = 0; n < 4; n++) {
            int r = row0 + mrow0 + s * 16 + gid;
            int c0 = ncol0 + n * 8 + 2 * tig;     // even
            if (r < M)
                e1h[(size_t)r * 64 + (c0 >> 1)] =
                    __floats2half2_rn(acc[s][n][0], acc[s][n][1]);
            if (r + 8 < M)
                e1h[(size_t)(r + 8) * 64 + (c0 >> 1)] =
                    __floats2half2_rn(acc[s][n][2], acc[s][n][3]);
        }
    }
}

// ---------------------------------------------------------------------------
extern "C" void kernel_launch(void* const* d_in, const int* in_sizes, int n_in,
                              void* d_out, int out_size) {
    const float* x    = (const float*)d_in[0];   // [100000,128]
    const int*   seq  = (const int*)d_in[1];     // [50000,32]
    const int*   useq = (const int*)d_in[2];     // [100000,16]
    const float* w1   = (const float*)d_in[4];   // [128,128]
    const float* w2   = (const float*)d_in[5];   // [128,128]
    const float* w3   = (const float*)d_in[6];   // [128,128]
    float* out = (float*)d_out;

    void *p_xh, *p_edge_pre, *p_e1h;
    cudaGetSymbolAddress(&p_xh, g_xh);
    cudaGetSymbolAddress(&p_edge_pre, g_edge_pre);
    cudaGetSymbolAddress(&p_e1h, g_e1h);

    cudaFuncSetAttribute(k_dualgemm,
                         cudaFuncAttributeMaxDynamicSharedMemorySize,
                         SMEM_TOTAL);

    k_internw<<<1, 512>>>(w3);

    // x -> fp16 table
    {
        int n4 = N_NODESC * 32;
        k_tohalf<<<(n4 + 255) / 256, 256>>>((const float4*)x, (uint2*)p_xh, n4);
    }

    // edge_pre[e] = masked-mean_a x_h[seq[e,a]]  (fp32 accumulate)
    k_gather_h<32><<<(N_EDGES + 7) / 8, 256>>>((const uint2*)p_xh, seq,
                                               (float4*)p_edge_pre, N_EDGES);

    // e1 = relu(s * edge_pre @ W1) @ W2   (tf32 mma.sync, fp16 out)
    k_dualgemm<<<TILES, 512, SMEM_TOTAL>>>((const float*)p_edge_pre, w1, w2,
                                           (__half2*)p_e1h, N_EDGES);

    // out[n] = masked-mean_k e1_h[useq[n,k]]
    k_gather_h<16><<<(N_NODESC + 7) / 8, 256>>>((const uint2*)p_e1h, useq,
                                                (float4*)out, N_NODESC);
}